// round 1
// baseline (speedup 1.0000x reference)
#include <cuda_runtime.h>
#include <cstdint>
#include <cstddef>

// Problem constants (B, NQ, NK, DQK=DV=64)
#define NB   8
#define NQ_  4096
#define NK_  4096
#define DH   64

#define BQ   64      // q rows per block
#define BK   128     // k cols per tile

// smem strides (floats), padded against bank conflicts
#define QS_STR 68
#define KS_STR 132
#define VS_STR 68
#define PS_STR 68

#define QS_OFF 0
#define KS_OFF (QS_OFF + 64*QS_STR)      // Qs: [d][r]   64x64
#define VS_OFF (KS_OFF + 64*KS_STR)      // Ks: [d][c]   64x128
#define PS_OFF (VS_OFF + 128*VS_STR)     // Vs: [k][v]   128x64
#define MS_OFF (PS_OFF + 128*PS_STR)     // Ps: [k][r]   128x64 (P transposed)
#define LS_OFF (MS_OFF + 64)
#define SMEM_FLOATS (LS_OFF + 64)
#define SMEM_BYTES  (SMEM_FLOATS * 4)    // 121,344 B

typedef unsigned long long ull;

// ---- packed fp32x2 helpers (Blackwell FFMA2 path) ----
__device__ __forceinline__ ull pk2(float lo, float hi) {
    ull r;
    asm("mov.b64 %0, {%1, %2};"
        : "=l"(r) : "r"(__float_as_uint(lo)), "r"(__float_as_uint(hi)));
    return r;
}
__device__ __forceinline__ float2 up2(ull v) {
    unsigned lo, hi;
    asm("mov.b64 {%0, %1}, %2;" : "=r"(lo), "=r"(hi) : "l"(v));
    return make_float2(__uint_as_float(lo), __uint_as_float(hi));
}
__device__ __forceinline__ void fma2(ull& c, ull a, ull b) {
    asm("fma.rn.f32x2 %0, %1, %2, %0;" : "+l"(c) : "l"(a), "l"(b));
}

// s[4][8] = 0.125 * (Q rows ty*4..+4) . (K cols tx*8..+8), over d=64
__device__ __forceinline__ void gemm_qk(const float* __restrict__ Qs,
                                        const float* __restrict__ Ks,
                                        int tx, int ty, float s[4][8])
{
    ull c2[4][4];
#pragma unroll
    for (int i = 0; i < 4; i++)
#pragma unroll
        for (int j = 0; j < 4; j++) c2[i][j] = 0ull;

#pragma unroll 8
    for (int d = 0; d < DH; d++) {
        float4 a  = *(const float4*)(Qs + d*QS_STR + ty*4);
        float4 b0 = *(const float4*)(Ks + d*KS_STR + tx*8);
        float4 b1 = *(const float4*)(Ks + d*KS_STR + tx*8 + 4);
        ull bb0 = pk2(b0.x, b0.y), bb1 = pk2(b0.z, b0.w);
        ull bb2 = pk2(b1.x, b1.y), bb3 = pk2(b1.z, b1.w);
        float ar[4] = {a.x, a.y, a.z, a.w};
#pragma unroll
        for (int i = 0; i < 4; i++) {
            ull av = pk2(ar[i], ar[i]);
            fma2(c2[i][0], av, bb0);
            fma2(c2[i][1], av, bb1);
            fma2(c2[i][2], av, bb2);
            fma2(c2[i][3], av, bb3);
        }
    }
#pragma unroll
    for (int i = 0; i < 4; i++)
#pragma unroll
        for (int j = 0; j < 4; j++) {
            float2 p = up2(c2[i][j]);
            s[i][2*j]   = p.x * 0.125f;   // 1/sqrt(64)
            s[i][2*j+1] = p.y * 0.125f;
        }
}

__global__ void __launch_bounds__(256, 1)
attn_causal_kernel(const float* __restrict__ Q, const float* __restrict__ K,
                   const float* __restrict__ V, float* __restrict__ O,
                   float* __restrict__ W)
{
    extern __shared__ float sm[];
    float* Qs  = sm + QS_OFF;
    float* Ks  = sm + KS_OFF;
    float* Vs  = sm + VS_OFF;
    float* Ps  = sm + PS_OFF;
    float* m_s = sm + MS_OFF;
    float* l_s = sm + LS_OFF;

    const int tid = threadIdx.x;
    const int tx = tid & 15, ty = tid >> 4;
    const int bid = blockIdx.x;
    const int qt = 63 - (bid >> 3);    // heavy q-tiles launch first
    const int b  = bid & 7;
    const int q0 = qt * BQ;
    const int KT = (qt >> 1) + 1;      // k-tiles needed to cover causal region

    const float* Qb = Q + (size_t)(b*NQ_ + q0) * DH;
    const float* Kb = K + (size_t)b * NK_ * DH;
    const float* Vb = V + (size_t)b * NK_ * DH;
    float* Wb = W ? W + ((size_t)b*NQ_ + q0) * NK_ : (float*)0;

    // -------- zero-fill strictly-future (masked) weight columns --------
    if (Wb) {
        const int zc0 = KT * BK;
        const int nz4 = (NK_ - zc0) >> 2;
        if (nz4 > 0) {
            const int wid = tid >> 5, lane = tid & 31;
            const float4 z = make_float4(0.f, 0.f, 0.f, 0.f);
            for (int r = wid; r < BQ; r += 8) {
                float4* rp = (float4*)(Wb + (size_t)r*NK_ + zc0);
                for (int c = lane; c < nz4; c += 32) rp[c] = z;
            }
        }
    }

    // -------- load Q tile transposed: Qs[d][r] --------
#pragma unroll
    for (int t = 0; t < 4; t++) {
        int idx4 = tid + 256*t;
        int r = idx4 >> 4;
        int d = (idx4 & 15) << 2;
        float4 v = *(const float4*)(Qb + (size_t)r*DH + d);
        Qs[(d+0)*QS_STR + r] = v.x;
        Qs[(d+1)*QS_STR + r] = v.y;
        Qs[(d+2)*QS_STR + r] = v.z;
        Qs[(d+3)*QS_STR + r] = v.w;
    }
    if (tid < BQ) { m_s[tid] = -INFINITY; l_s[tid] = 0.f; }

    // ======== pass 1: raw logits (to gmem scratch) + online softmax stats ========
    for (int kt = 0; kt < KT; kt++) {
        const int k0 = kt * BK;
        __syncthreads();
        // load K tile transposed: Ks[d][c]
#pragma unroll
        for (int t = 0; t < 8; t++) {
            int idx4 = tid + 256*t;
            int c = idx4 >> 4;
            int d = (idx4 & 15) << 2;
            float4 v = *(const float4*)(Kb + (size_t)(k0 + c)*DH + d);
            Ks[(d+0)*KS_STR + c] = v.x;
            Ks[(d+1)*KS_STR + c] = v.y;
            Ks[(d+2)*KS_STR + c] = v.z;
            Ks[(d+3)*KS_STR + c] = v.w;
        }
        __syncthreads();

        float s[4][8];
        gemm_qk(Qs, Ks, tx, ty, s);

        if (kt == KT-1) {                      // causal mask (matches ref: +(-1e9))
#pragma unroll
            for (int i = 0; i < 4; i++)
#pragma unroll
                for (int j = 0; j < 8; j++)
                    if (k0 + tx*8 + j > q0 + ty*4 + i) s[i][j] -= 1e9f;
        }

        if (Wb) {                              // stash raw logits in W (scratch)
#pragma unroll
            for (int i = 0; i < 4; i++) {
                float4* rp = (float4*)(Wb + (size_t)(ty*4+i)*NK_ + k0 + tx*8);
                rp[0] = make_float4(s[i][0], s[i][1], s[i][2], s[i][3]);
                rp[1] = make_float4(s[i][4], s[i][5], s[i][6], s[i][7]);
            }
        }

        // per-row online max / sumexp (16 lanes per row-group, same warp half)
#pragma unroll
        for (int i = 0; i < 4; i++) {
            const int r = ty*4 + i;
            float tmax = s[i][0];
#pragma unroll
            for (int j = 1; j < 8; j++) tmax = fmaxf(tmax, s[i][j]);
#pragma unroll
            for (int off = 8; off; off >>= 1)
                tmax = fmaxf(tmax, __shfl_xor_sync(0xffffffffu, tmax, off));
            const float m_old = m_s[r];
            const float m_new = fmaxf(m_old, tmax);
            float rs = 0.f;
#pragma unroll
            for (int j = 0; j < 8; j++) rs += __expf(s[i][j] - m_new);
#pragma unroll
            for (int off = 8; off; off >>= 1)
                rs += __shfl_xor_sync(0xffffffffu, rs, off);
            if (tx == 0) {
                l_s[r] = l_s[r] * __expf(m_old - m_new) + rs;
                m_s[r] = m_new;
            }
        }
    }

    // ======== pass 2: normalized weights + O = P @ V ========
    ull o2[4][2];
#pragma unroll
    for (int i = 0; i < 4; i++) { o2[i][0] = 0ull; o2[i][1] = 0ull; }

    for (int kt = 0; kt < KT; kt++) {
        const int k0 = kt * BK;
        __syncthreads();   // prior GEMM2 readers done with Ps/Vs; pass1 stats visible
        // load V tile: Vs[k][v]
#pragma unroll
        for (int t = 0; t < 8; t++) {
            int idx4 = tid + 256*t;
            int k = idx4 >> 4;
            int d = (idx4 & 15) << 2;
            float4 v = *(const float4*)(Vb + (size_t)(k0 + k)*DH + d);
            *(float4*)(Vs + k*VS_STR + d) = v;
        }

        if (Wb) {
            // read raw logits back, normalize, write weights, stage P^T in smem
#pragma unroll
            for (int t = 0; t < 8; t++) {
                int idx4 = tid + 256*t;
                int r  = idx4 >> 5;
                int c4 = (idx4 & 31) << 2;
                float m  = m_s[r];
                float li = __fdividef(1.f, l_s[r]);
                float4* gp = (float4*)(Wb + (size_t)r*NK_ + k0 + c4);
                float4 sv = *gp;
                float4 wv;
                wv.x = __expf(sv.x - m) * li;
                wv.y = __expf(sv.y - m) * li;
                wv.z = __expf(sv.z - m) * li;
                wv.w = __expf(sv.w - m) * li;
                *gp = wv;
                Ps[(c4+0)*PS_STR + r] = wv.x;
                Ps[(c4+1)*PS_STR + r] = wv.y;
                Ps[(c4+2)*PS_STR + r] = wv.z;
                Ps[(c4+3)*PS_STR + r] = wv.w;
            }
        } else {
            // fallback (no weights output): recompute S instead of gmem readback
#pragma unroll
            for (int t = 0; t < 8; t++) {
                int idx4 = tid + 256*t;
                int c = idx4 >> 4;
                int d = (idx4 & 15) << 2;
                float4 v = *(const float4*)(Kb + (size_t)(k0 + c)*DH + d);
                Ks[(d+0)*KS_STR + c] = v.x;
                Ks[(d+1)*KS_STR + c] = v.y;
                Ks[(d+2)*KS_STR + c] = v.z;
                Ks[(d+3)*KS_STR + c] = v.w;
            }
            __syncthreads();
            float s[4][8];
            gemm_qk(Qs, Ks, tx, ty, s);
            if (kt == KT-1) {
#pragma unroll
                for (int i = 0; i < 4; i++)
#pragma unroll
                    for (int j = 0; j < 8; j++)
                        if (k0 + tx*8 + j > q0 + ty*4 + i) s[i][j] -= 1e9f;
            }
#pragma unroll
            for (int i = 0; i < 4; i++) {
                int r = ty*4 + i;
                float m  = m_s[r];
                float li = __fdividef(1.f, l_s[r]);
#pragma unroll
                for (int j = 0; j < 8; j++)
                    Ps[(tx*8+j)*PS_STR + r] = __expf(s[i][j] - m) * li;
            }
        }
        __syncthreads();

        // O(64x64) += P^T-staged(128xk, 64 rows) @ V(128x64), f32x2 packed
#pragma unroll 8
        for (int kk = 0; kk < BK; kk++) {
            float4 a = *(const float4*)(Ps + kk*PS_STR + ty*4);
            ull b0 = *(const ull*)(Vs + kk*VS_STR + tx*4);
            ull b1 = *(const ull*)(Vs + kk*VS_STR + tx*4 + 2);
            float ar[4] = {a.x, a.y, a.z, a.w};
#pragma unroll
            for (int i = 0; i < 4; i++) {
                ull av = pk2(ar[i], ar[i]);
                fma2(o2[i][0], av, b0);
                fma2(o2[i][1], av, b1);
            }
        }
    }

    if (O) {
#pragma unroll
        for (int i = 0; i < 4; i++) {
            float2 p0 = up2(o2[i][0]);
            float2 p1 = up2(o2[i][1]);
            *(float4*)(O + ((size_t)b*NQ_ + q0 + ty*4 + i)*DH + tx*4) =
                make_float4(p0.x, p0.y, p1.x, p1.y);
        }
    }
}

extern "C" void kernel_launch(void* const* d_in, const int* in_sizes, int n_in,
                              void* d_out, int out_size)
{
    const float* Q = (const float*)d_in[0];
    const float* K = (const float*)d_in[1];
    const float* V = (const float*)d_in[2];
    // d_in[3] = mask, unused: causal structure is known analytically and
    // reproduces the reference's "+ mask * (-1e9)" exactly.

    const long long OUTE = (long long)NB * NQ_ * DH;    //   2,097,152
    const long long WE   = (long long)NB * NQ_ * NK_;   // 134,217,728

    float* o = 0;
    float* w = 0;
    long long osz = (long long)out_size;
    if (osz >= OUTE + WE) {          // tuple (output, attention_weights)
        o = (float*)d_out;
        w = (float*)d_out + OUTE;
    } else if (osz == WE) {          // weights only
        w = (float*)d_out;
    } else {                          // output only
        o = (float*)d_out;
    }

    cudaFuncSetAttribute(attn_causal_kernel,
                         cudaFuncAttributeMaxDynamicSharedMemorySize, SMEM_BYTES);
    attn_causal_kernel<<<NB * 64, 256, SMEM_BYTES>>>(Q, K, V, o, w);
}